// round 1
// baseline (speedup 1.0000x reference)
#include <cuda_runtime.h>
#include <math.h>

#define N_NODES 50000
#define N_EDGES 600000
#define NF      128
#define NG      512
#define NC      10
#define BN_EPS  1e-5f

// ---------------- scratch (device globals; no allocation allowed) ----------
__device__ int      g_deg [N_NODES];
__device__ float    g_dinv[N_NODES];
__device__ float    g_y   [N_NODES * NF];
__device__ float    g_acc [N_NODES * NF];
__device__ float    g_h   [N_NODES * NF];
__device__ unsigned g_gmax[NG * NF];
__device__ float    g_g   [NG * NF];
__device__ float    g_m1  [NG * NF];   // MLP1 out
__device__ float    g_m2  [NG * 64];   // MLP2 out

// ---------------- helpers --------------------------------------------------
__device__ __forceinline__ unsigned enc_f(float v) {
    unsigned u = __float_as_uint(v);
    return (u & 0x80000000u) ? ~u : (u | 0x80000000u);
}
__device__ __forceinline__ float dec_f(unsigned u) {
    return (u & 0x80000000u) ? __uint_as_float(u & 0x7FFFFFFFu)
                             : __uint_as_float(~u);
}

// ---------------- trivial kernels ------------------------------------------
__global__ void zero_f4(float4* p, int n4) {
    int i = blockIdx.x * blockDim.x + threadIdx.x;
    if (i < n4) p[i] = make_float4(0.f, 0.f, 0.f, 0.f);
}
__global__ void zero_u(unsigned* p, int n) {
    int i = blockIdx.x * blockDim.x + threadIdx.x;
    if (i < n) p[i] = 0u;
}
__global__ void zero_i(int* p, int n) {
    int i = blockIdx.x * blockDim.x + threadIdx.x;
    if (i < n) p[i] = 0;
}
__global__ void deg_count(const int* __restrict__ dst) {
    int e = blockIdx.x * blockDim.x + threadIdx.x;
    if (e < N_EDGES) atomicAdd(&g_deg[dst[e]], 1);
}
__global__ void calc_dinv() {
    int i = blockIdx.x * blockDim.x + threadIdx.x;
    if (i < N_NODES) g_dinv[i] = rsqrtf((float)g_deg[i] + 1.0f);
}

// ---------------- GEMM: out[r,c] = sum_k A[r,k]*W[k,c]  (K = 128, N = 128) --
// epilogue: optional row-scale by dinv, optional +bias, optional relu
// BM=64 rows, BN=128 cols, BK=16, 256 threads, thread tile 8x4
__global__ __launch_bounds__(256)
void gemm128(const float* __restrict__ A, const float* __restrict__ W,
             float* __restrict__ out,
             const float* __restrict__ dinv, const float* __restrict__ bias,
             int nrows, int do_relu)
{
    __shared__ float Xs[64][20];    // [row][k] padded
    __shared__ float Ws[16][128];   // [k][col]

    const int tid  = threadIdx.x;
    const int tcol = tid & 31;      // covers cols tcol*4 .. +3
    const int trow = tid >> 5;      // covers rows trow*8 .. +7
    const int row0 = blockIdx.x * 64;

    float acc[8][4];
    #pragma unroll
    for (int r = 0; r < 8; ++r)
        #pragma unroll
        for (int c = 0; c < 4; ++c) acc[r][c] = 0.f;

    const int lr  = tid >> 2;       // 0..63  (loader row)
    const int lk4 = tid & 3;        // 0..3   (loader k-float4)

    for (int k0 = 0; k0 < 128; k0 += 16) {
        // load X tile 64x16
        float4 xv = make_float4(0.f, 0.f, 0.f, 0.f);
        int grow = row0 + lr;
        if (grow < nrows)
            xv = *reinterpret_cast<const float4*>(&A[grow * 128 + k0 + lk4 * 4]);
        *reinterpret_cast<float4*>(&Xs[lr][lk4 * 4]) = xv;
        // load W tile 16x128 (2 float4 per thread)
        #pragma unroll
        for (int it = 0; it < 2; ++it) {
            int idx = tid + it * 256;     // 0..511
            int k   = idx >> 5;
            int c4  = idx & 31;
            *reinterpret_cast<float4*>(&Ws[k][c4 * 4]) =
                *reinterpret_cast<const float4*>(&W[(k0 + k) * 128 + c4 * 4]);
        }
        __syncthreads();

        #pragma unroll
        for (int kk = 0; kk < 16; ++kk) {
            float4 wv = *reinterpret_cast<const float4*>(&Ws[kk][tcol * 4]);
            #pragma unroll
            for (int r = 0; r < 8; ++r) {
                float xvv = Xs[trow * 8 + r][kk];
                acc[r][0] += xvv * wv.x;
                acc[r][1] += xvv * wv.y;
                acc[r][2] += xvv * wv.z;
                acc[r][3] += xvv * wv.w;
            }
        }
        __syncthreads();
    }

    float4 bv = make_float4(0.f, 0.f, 0.f, 0.f);
    if (bias) bv = *reinterpret_cast<const float4*>(&bias[tcol * 4]);

    #pragma unroll
    for (int r = 0; r < 8; ++r) {
        int grow = row0 + trow * 8 + r;
        if (grow >= nrows) continue;
        float s = dinv ? dinv[grow] : 1.0f;
        float4 o;
        o.x = acc[r][0] * s + bv.x;
        o.y = acc[r][1] * s + bv.y;
        o.z = acc[r][2] * s + bv.z;
        o.w = acc[r][3] * s + bv.w;
        if (do_relu) {
            o.x = fmaxf(o.x, 0.f); o.y = fmaxf(o.y, 0.f);
            o.z = fmaxf(o.z, 0.f); o.w = fmaxf(o.w, 0.f);
        }
        *reinterpret_cast<float4*>(&out[grow * 128 + tcol * 4]) = o;
    }
}

// ---------------- edge scatter: acc[dst] += y[src] (one warp per edge) -----
__global__ __launch_bounds__(256)
void scatter_add(const int* __restrict__ src, const int* __restrict__ dst,
                 const float* __restrict__ y, float* __restrict__ acc)
{
    int e    = blockIdx.x * 8 + (threadIdx.x >> 5);
    int lane = threadIdx.x & 31;
    if (e >= N_EDGES) return;
    int s = src[e], d = dst[e];
    float4 v = *reinterpret_cast<const float4*>(&y[s * 128 + lane * 4]);
    float* a = &acc[d * 128 + lane * 4];
    atomicAdd(a + 0, v.x);
    atomicAdd(a + 1, v.y);
    atomicAdd(a + 2, v.z);
    atomicAdd(a + 3, v.w);
}

// ---------------- finalize: h = relu(dinv*(acc + y) + b) -------------------
__global__ __launch_bounds__(256)
void finalize(const float* __restrict__ y, const float* __restrict__ acc,
              const float* __restrict__ bias, float* __restrict__ h)
{
    int i = blockIdx.x * blockDim.x + threadIdx.x;   // over N_NODES*32
    if (i >= N_NODES * 32) return;
    int node = i >> 5, lane = i & 31;
    float  di = g_dinv[node];
    float4 av = *reinterpret_cast<const float4*>(&acc[node * 128 + lane * 4]);
    float4 yv = *reinterpret_cast<const float4*>(&y  [node * 128 + lane * 4]);
    float4 bv = *reinterpret_cast<const float4*>(&bias[lane * 4]);
    float4 o;
    o.x = fmaxf(di * (av.x + yv.x) + bv.x, 0.f);
    o.y = fmaxf(di * (av.y + yv.y) + bv.y, 0.f);
    o.z = fmaxf(di * (av.z + yv.z) + bv.z, 0.f);
    o.w = fmaxf(di * (av.w + yv.w) + bv.w, 0.f);
    *reinterpret_cast<float4*>(&h[node * 128 + lane * 4]) = o;
}

// ---------------- BN (eval) + per-graph max via encoded atomicMax ----------
__global__ __launch_bounds__(256)
void bn_max(const float* __restrict__ h, const int* __restrict__ batch,
            const float* __restrict__ gamma, const float* __restrict__ beta,
            const float* __restrict__ rmean, const float* __restrict__ rvar)
{
    int i = blockIdx.x * blockDim.x + threadIdx.x;   // over N_NODES*32
    if (i >= N_NODES * 32) return;
    int node = i >> 5, lane = i & 31;
    int c = lane * 4;
    float4 hv = *reinterpret_cast<const float4*>(&h[node * 128 + c]);
    float4 gm = *reinterpret_cast<const float4*>(&gamma[c]);
    float4 bt = *reinterpret_cast<const float4*>(&beta[c]);
    float4 mu = *reinterpret_cast<const float4*>(&rmean[c]);
    float4 va = *reinterpret_cast<const float4*>(&rvar[c]);
    float4 v;
    v.x = (hv.x - mu.x) * rsqrtf(va.x + BN_EPS) * gm.x + bt.x;
    v.y = (hv.y - mu.y) * rsqrtf(va.y + BN_EPS) * gm.y + bt.y;
    v.z = (hv.z - mu.z) * rsqrtf(va.z + BN_EPS) * gm.z + bt.z;
    v.w = (hv.w - mu.w) * rsqrtf(va.w + BN_EPS) * gm.w + bt.w;
    unsigned* p = &g_gmax[batch[node] * 128 + c];
    atomicMax(p + 0, enc_f(v.x));
    atomicMax(p + 1, enc_f(v.y));
    atomicMax(p + 2, enc_f(v.z));
    atomicMax(p + 3, enc_f(v.w));
}

__global__ void decode_g() {
    int i = blockIdx.x * blockDim.x + threadIdx.x;
    if (i < NG * NF) g_g[i] = dec_f(g_gmax[i]);
}

// ---------------- small GEMM (one block per row) ---------------------------
__global__ void small_gemm(const float* __restrict__ A, const float* __restrict__ W,
                           const float* __restrict__ b, float* __restrict__ out,
                           int K, int ncols, int do_relu)
{
    __shared__ float xs[128];
    int row = blockIdx.x;
    for (int k = threadIdx.x; k < K; k += blockDim.x) xs[k] = A[row * K + k];
    __syncthreads();
    int c = threadIdx.x;
    if (c < ncols) {
        float s = b[c];
        for (int k = 0; k < K; ++k) s += xs[k] * W[k * ncols + c];
        out[row * ncols + c] = do_relu ? fmaxf(s, 0.f) : s;
    }
}

// ---------------- launch ---------------------------------------------------
extern "C" void kernel_launch(void* const* d_in, const int* in_sizes, int n_in,
                              void* d_out, int out_size)
{
    const float* x     = (const float*)d_in[0];
    const int*   ei    = (const int*)  d_in[1];
    const int*   batch = (const int*)  d_in[2];
    const float* W1 = (const float*)d_in[3];  const float* b1 = (const float*)d_in[4];
    const float* W2 = (const float*)d_in[5];  const float* b2 = (const float*)d_in[6];
    const float* W3 = (const float*)d_in[7];  const float* b3 = (const float*)d_in[8];
    const float* gamma = (const float*)d_in[9];
    const float* beta  = (const float*)d_in[10];
    const float* rmean = (const float*)d_in[11];
    const float* rvar  = (const float*)d_in[12];
    const float* lw1 = (const float*)d_in[13]; const float* lb1 = (const float*)d_in[14];
    const float* lw2 = (const float*)d_in[15]; const float* lb2 = (const float*)d_in[16];
    const float* lw3 = (const float*)d_in[17]; const float* lb3 = (const float*)d_in[18];
    float* out = (float*)d_out;

    const int* src = ei;
    const int* dst = ei + N_EDGES;

    // resolve device-symbol addresses (host API, cheap, not an allocation)
    void *p_deg, *p_dinv, *p_y, *p_acc, *p_h, *p_gmax, *p_g, *p_m1, *p_m2;
    cudaGetSymbolAddress(&p_deg,  g_deg);
    cudaGetSymbolAddress(&p_dinv, g_dinv);
    cudaGetSymbolAddress(&p_y,    g_y);
    cudaGetSymbolAddress(&p_acc,  g_acc);
    cudaGetSymbolAddress(&p_h,    g_h);
    cudaGetSymbolAddress(&p_gmax, g_gmax);
    cudaGetSymbolAddress(&p_g,    g_g);
    cudaGetSymbolAddress(&p_m1,   g_m1);
    cudaGetSymbolAddress(&p_m2,   g_m2);
    float* y   = (float*)p_y;
    float* acc = (float*)p_acc;
    float* h   = (float*)p_h;

    const int EB   = (N_EDGES + 255) / 256;
    const int NB   = (N_NODES + 255) / 256;
    const int GRID_GEMM = (N_NODES + 63) / 64;
    const int GRID_NF4  = (N_NODES * 32 + 255) / 256;   // node*lane threads
    const int GRID_ACC4 = (N_NODES * 32 + 255) / 256;   // 1.6M float4

    // degree + dinv
    zero_i<<<NB, 256>>>((int*)p_deg, N_NODES);
    deg_count<<<EB, 256>>>(dst);
    calc_dinv<<<NB, 256>>>();
    zero_u<<<(NG * NF + 255) / 256, 256>>>((unsigned*)p_gmax, NG * NF);

    const float* layer_in[3] = { x, h, h };
    const float* Ws_[3] = { W1, W2, W3 };
    const float* bs_[3] = { b1, b2, b3 };

    for (int L = 0; L < 3; ++L) {
        zero_f4<<<GRID_ACC4, 256>>>((float4*)acc, N_NODES * 32);
        gemm128<<<GRID_GEMM, 256>>>(layer_in[L], Ws_[L], y,
                                    (const float*)p_dinv, nullptr, N_NODES, 0);
        scatter_add<<<(N_EDGES + 7) / 8, 256>>>(src, dst, y, acc);
        finalize<<<GRID_NF4, 256>>>(y, acc, bs_[L], h);
    }

    // BN + per-graph max
    bn_max<<<GRID_NF4, 256>>>(h, batch, gamma, beta, rmean, rvar);
    decode_g<<<(NG * NF + 255) / 256, 256>>>();

    // MLP head
    gemm128<<<(NG + 63) / 64, 256>>>((const float*)p_g, lw1, (float*)p_m1,
                                     nullptr, lb1, NG, 1);
    small_gemm<<<NG, 64>>>((const float*)p_m1, lw2, lb2, (float*)p_m2, 128, 64, 1);
    small_gemm<<<NG, 64>>>((const float*)p_m2, lw3, lb3, out, 64, NC, 0);
}

// round 2
// speedup vs baseline: 1.7548x; 1.7548x over previous
#include <cuda_runtime.h>
#include <math.h>

#define N_NODES 50000
#define N_EDGES 600000
#define NF      128
#define NG      512
#define NC      10
#define BN_EPS  1e-5f

// ---------------- scratch (device globals) ---------------------------------
__device__ int      g_deg   [N_NODES];
__device__ int      g_rowptr[N_NODES + 1];
__device__ int      g_cursor[N_NODES];
__device__ int      g_csrc  [N_EDGES];          // CSR: src ids grouped by dst
__device__ float    g_dinv  [N_NODES];
__device__ float    g_y     [N_NODES * NF];
__device__ float    g_h     [N_NODES * NF];
__device__ unsigned g_gmax  [NG * NF];
__device__ float    g_g     [NG * NF];
__device__ float    g_m1    [NG * NF];
__device__ float    g_m2    [NG * 64];

// ---------------- helpers --------------------------------------------------
__device__ __forceinline__ unsigned enc_f(float v) {
    unsigned u = __float_as_uint(v);
    return (u & 0x80000000u) ? ~u : (u | 0x80000000u);
}
__device__ __forceinline__ float dec_f(unsigned u) {
    return (u & 0x80000000u) ? __uint_as_float(u & 0x7FFFFFFFu)
                             : __uint_as_float(~u);
}

// ---------------- CSR build -------------------------------------------------
__global__ void zero_i(int* p, int n) {
    int i = blockIdx.x * blockDim.x + threadIdx.x;
    if (i < n) p[i] = 0;
}
__global__ void zero_u(unsigned* p, int n) {
    int i = blockIdx.x * blockDim.x + threadIdx.x;
    if (i < n) p[i] = 0u;
}
__global__ void deg_count(const int* __restrict__ dst) {
    int e = blockIdx.x * blockDim.x + threadIdx.x;
    if (e < N_EDGES) atomicAdd(&g_deg[dst[e]], 1);
}
// single-block exclusive scan over g_deg -> g_rowptr (+ copy to g_cursor), dinv
__global__ __launch_bounds__(1024) void scan_deg() {
    __shared__ int sums[1024];
    const int CH = (N_NODES + 1023) / 1024;   // 49
    int t = threadIdx.x;
    int base = t * CH;
    int s = 0;
    for (int i = 0; i < CH; ++i) {
        int idx = base + i;
        if (idx < N_NODES) s += g_deg[idx];
    }
    sums[t] = s;
    __syncthreads();
    for (int off = 1; off < 1024; off <<= 1) {
        int v = 0;
        if (t >= off) v = sums[t - off];
        __syncthreads();
        if (t >= off) sums[t] += v;
        __syncthreads();
    }
    int run = (t == 0) ? 0 : sums[t - 1];
    for (int i = 0; i < CH; ++i) {
        int idx = base + i;
        if (idx < N_NODES) {
            g_rowptr[idx] = run;
            g_cursor[idx] = run;
            g_dinv[idx]   = rsqrtf((float)g_deg[idx] + 1.0f);
            run += g_deg[idx];
        }
    }
    if (t == 1023) g_rowptr[N_NODES] = run;
}
__global__ void csr_fill(const int* __restrict__ src, const int* __restrict__ dst) {
    int e = blockIdx.x * blockDim.x + threadIdx.x;
    if (e < N_EDGES) {
        int pos = atomicAdd(&g_cursor[dst[e]], 1);
        g_csrc[pos] = src[e];
    }
}

// ---------------- GEMM: out = (A @ W) * dinv[row]  (K=N=128) ---------------
// 128x128 block tile, 256 threads, 8x8 per thread, BK=8
__global__ __launch_bounds__(256)
void gemm_rs(const float* __restrict__ A, const float* __restrict__ W,
             float* __restrict__ out,
             const float* __restrict__ dinv, const float* __restrict__ bias,
             int nrows, int do_relu)
{
    __shared__ float Xs[8][132];    // [k][row], padded
    __shared__ float Ws[8][128];    // [k][col]

    const int tid  = threadIdx.x;
    const int trow = tid >> 4;      // 0..15 -> rows trow*8..+7
    const int tcol = tid & 15;      // 0..15 -> cols tcol*8..+7
    const int row0 = blockIdx.x * 128;

    float acc[8][8];
    #pragma unroll
    for (int r = 0; r < 8; ++r)
        #pragma unroll
        for (int c = 0; c < 8; ++c) acc[r][c] = 0.f;

    const int lr = tid >> 1;        // 0..127 (A-loader row)
    const int lk = (tid & 1) * 4;   // 0 or 4 (A-loader k)
    const int wk = tid >> 5;        // 0..7   (W-loader k)
    const int wc = (tid & 31) * 4;  // W-loader col

    for (int k0 = 0; k0 < 128; k0 += 8) {
        float4 av = make_float4(0.f, 0.f, 0.f, 0.f);
        int gr = row0 + lr;
        if (gr < nrows)
            av = *reinterpret_cast<const float4*>(&A[gr * 128 + k0 + lk]);
        Xs[lk + 0][lr] = av.x;
        Xs[lk + 1][lr] = av.y;
        Xs[lk + 2][lr] = av.z;
        Xs[lk + 3][lr] = av.w;
        *reinterpret_cast<float4*>(&Ws[wk][wc]) =
            *reinterpret_cast<const float4*>(&W[(k0 + wk) * 128 + wc]);
        __syncthreads();

        #pragma unroll
        for (int kk = 0; kk < 8; ++kk) {
            float a[8], b[8];
            *reinterpret_cast<float4*>(&a[0]) = *reinterpret_cast<float4*>(&Xs[kk][trow * 8]);
            *reinterpret_cast<float4*>(&a[4]) = *reinterpret_cast<float4*>(&Xs[kk][trow * 8 + 4]);
            *reinterpret_cast<float4*>(&b[0]) = *reinterpret_cast<float4*>(&Ws[kk][tcol * 8]);
            *reinterpret_cast<float4*>(&b[4]) = *reinterpret_cast<float4*>(&Ws[kk][tcol * 8 + 4]);
            #pragma unroll
            for (int r = 0; r < 8; ++r)
                #pragma unroll
                for (int c = 0; c < 8; ++c)
                    acc[r][c] += a[r] * b[c];
        }
        __syncthreads();
    }

    #pragma unroll
    for (int r = 0; r < 8; ++r) {
        int grow = row0 + trow * 8 + r;
        if (grow >= nrows) continue;
        float s = dinv ? dinv[grow] : 1.0f;
        #pragma unroll
        for (int c4 = 0; c4 < 2; ++c4) {
            float4 o;
            int cc = tcol * 8 + c4 * 4;
            o.x = acc[r][c4 * 4 + 0] * s;
            o.y = acc[r][c4 * 4 + 1] * s;
            o.z = acc[r][c4 * 4 + 2] * s;
            o.w = acc[r][c4 * 4 + 3] * s;
            if (bias) {
                float4 bv = *reinterpret_cast<const float4*>(&bias[cc]);
                o.x += bv.x; o.y += bv.y; o.z += bv.z; o.w += bv.w;
            }
            if (do_relu) {
                o.x = fmaxf(o.x, 0.f); o.y = fmaxf(o.y, 0.f);
                o.z = fmaxf(o.z, 0.f); o.w = fmaxf(o.w, 0.f);
            }
            *reinterpret_cast<float4*>(&out[grow * 128 + cc]) = o;
        }
    }
}

// ---------------- aggregate (CSR gather) + fused epilogue ------------------
// MODE 0: h = relu(dinv*(sum + self) + bias)
// MODE 1: same, then BN(eval) + per-graph atomicMax (no h store)
template <int MODE>
__global__ __launch_bounds__(256)
void aggregate(const float* __restrict__ y, const float* __restrict__ bias,
               float* __restrict__ h,
               const int* __restrict__ batch,
               const float* __restrict__ gamma, const float* __restrict__ beta,
               const float* __restrict__ rmean, const float* __restrict__ rvar)
{
    int node = blockIdx.x * 8 + (threadIdx.x >> 5);
    int lane = threadIdx.x & 31;
    if (node >= N_NODES) return;

    int p0 = g_rowptr[node];
    int p1 = g_rowptr[node + 1];

    float4 a = make_float4(0.f, 0.f, 0.f, 0.f);
    int e = p0;
    for (; e + 4 <= p1; e += 4) {
        int s0 = g_csrc[e + 0];
        int s1 = g_csrc[e + 1];
        int s2 = g_csrc[e + 2];
        int s3 = g_csrc[e + 3];
        float4 v0 = *reinterpret_cast<const float4*>(&y[s0 * 128 + lane * 4]);
        float4 v1 = *reinterpret_cast<const float4*>(&y[s1 * 128 + lane * 4]);
        float4 v2 = *reinterpret_cast<const float4*>(&y[s2 * 128 + lane * 4]);
        float4 v3 = *reinterpret_cast<const float4*>(&y[s3 * 128 + lane * 4]);
        a.x += (v0.x + v1.x) + (v2.x + v3.x);
        a.y += (v0.y + v1.y) + (v2.y + v3.y);
        a.z += (v0.z + v1.z) + (v2.z + v3.z);
        a.w += (v0.w + v1.w) + (v2.w + v3.w);
    }
    for (; e < p1; ++e) {
        int s = g_csrc[e];
        float4 v = *reinterpret_cast<const float4*>(&y[s * 128 + lane * 4]);
        a.x += v.x; a.y += v.y; a.z += v.z; a.w += v.w;
    }

    float4 self = *reinterpret_cast<const float4*>(&y[node * 128 + lane * 4]);
    float  di   = g_dinv[node];
    int    c    = lane * 4;
    float4 bv   = *reinterpret_cast<const float4*>(&bias[c]);
    float4 o;
    o.x = fmaxf(di * (a.x + self.x) + bv.x, 0.f);
    o.y = fmaxf(di * (a.y + self.y) + bv.y, 0.f);
    o.z = fmaxf(di * (a.z + self.z) + bv.z, 0.f);
    o.w = fmaxf(di * (a.w + self.w) + bv.w, 0.f);

    if (MODE == 0) {
        *reinterpret_cast<float4*>(&h[node * 128 + c]) = o;
    } else {
        float4 gm = *reinterpret_cast<const float4*>(&gamma[c]);
        float4 bt = *reinterpret_cast<const float4*>(&beta[c]);
        float4 mu = *reinterpret_cast<const float4*>(&rmean[c]);
        float4 va = *reinterpret_cast<const float4*>(&rvar[c]);
        float4 v;
        v.x = (o.x - mu.x) * rsqrtf(va.x + BN_EPS) * gm.x + bt.x;
        v.y = (o.y - mu.y) * rsqrtf(va.y + BN_EPS) * gm.y + bt.y;
        v.z = (o.z - mu.z) * rsqrtf(va.z + BN_EPS) * gm.z + bt.z;
        v.w = (o.w - mu.w) * rsqrtf(va.w + BN_EPS) * gm.w + bt.w;
        unsigned* p = &g_gmax[batch[node] * 128 + c];
        atomicMax(p + 0, enc_f(v.x));
        atomicMax(p + 1, enc_f(v.y));
        atomicMax(p + 2, enc_f(v.z));
        atomicMax(p + 3, enc_f(v.w));
    }
}

__global__ void decode_g() {
    int i = blockIdx.x * blockDim.x + threadIdx.x;
    if (i < NG * NF) g_g[i] = dec_f(g_gmax[i]);
}

// ---------------- small GEMM (one block per row) ---------------------------
__global__ void small_gemm(const float* __restrict__ A, const float* __restrict__ W,
                           const float* __restrict__ b, float* __restrict__ out,
                           int K, int ncols, int do_relu)
{
    __shared__ float xs[128];
    int row = blockIdx.x;
    for (int k = threadIdx.x; k < K; k += blockDim.x) xs[k] = A[row * K + k];
    __syncthreads();
    int c = threadIdx.x;
    if (c < ncols) {
        float s = b[c];
        for (int k = 0; k < K; ++k) s += xs[k] * W[k * ncols + c];
        out[row * ncols + c] = do_relu ? fmaxf(s, 0.f) : s;
    }
}

// ---------------- launch ---------------------------------------------------
extern "C" void kernel_launch(void* const* d_in, const int* in_sizes, int n_in,
                              void* d_out, int out_size)
{
    const float* x     = (const float*)d_in[0];
    const int*   ei    = (const int*)  d_in[1];
    const int*   batch = (const int*)  d_in[2];
    const float* W1 = (const float*)d_in[3];  const float* b1 = (const float*)d_in[4];
    const float* W2 = (const float*)d_in[5];  const float* b2 = (const float*)d_in[6];
    const float* W3 = (const float*)d_in[7];  const float* b3 = (const float*)d_in[8];
    const float* gamma = (const float*)d_in[9];
    const float* beta  = (const float*)d_in[10];
    const float* rmean = (const float*)d_in[11];
    const float* rvar  = (const float*)d_in[12];
    const float* lw1 = (const float*)d_in[13]; const float* lb1 = (const float*)d_in[14];
    const float* lw2 = (const float*)d_in[15]; const float* lb2 = (const float*)d_in[16];
    const float* lw3 = (const float*)d_in[17]; const float* lb3 = (const float*)d_in[18];
    float* out = (float*)d_out;

    const int* src = ei;
    const int* dst = ei + N_EDGES;

    void *p_deg, *p_dinv, *p_y, *p_h, *p_gmax, *p_g, *p_m1, *p_m2;
    cudaGetSymbolAddress(&p_deg,  g_deg);
    cudaGetSymbolAddress(&p_dinv, g_dinv);
    cudaGetSymbolAddress(&p_y,    g_y);
    cudaGetSymbolAddress(&p_h,    g_h);
    cudaGetSymbolAddress(&p_gmax, g_gmax);
    cudaGetSymbolAddress(&p_g,    g_g);
    cudaGetSymbolAddress(&p_m1,   g_m1);
    cudaGetSymbolAddress(&p_m2,   g_m2);
    float* y = (float*)p_y;
    float* h = (float*)p_h;

    const int EB = (N_EDGES + 255) / 256;
    const int NB = (N_NODES + 255) / 256;
    const int GRID_GEMM = (N_NODES + 127) / 128;
    const int GRID_AGG  = (N_NODES + 7) / 8;

    // CSR build + dinv
    zero_i<<<NB, 256>>>((int*)p_deg, N_NODES);
    deg_count<<<EB, 256>>>(dst);
    scan_deg<<<1, 1024>>>();
    csr_fill<<<EB, 256>>>(src, dst);
    zero_u<<<(NG * NF + 255) / 256, 256>>>((unsigned*)p_gmax, NG * NF);

    // layer 1
    gemm_rs<<<GRID_GEMM, 256>>>(x, W1, y, (const float*)p_dinv, nullptr, N_NODES, 0);
    aggregate<0><<<GRID_AGG, 256>>>(y, b1, h, nullptr, nullptr, nullptr, nullptr, nullptr);
    // layer 2
    gemm_rs<<<GRID_GEMM, 256>>>(h, W2, y, (const float*)p_dinv, nullptr, N_NODES, 0);
    aggregate<0><<<GRID_AGG, 256>>>(y, b2, h, nullptr, nullptr, nullptr, nullptr, nullptr);
    // layer 3 + BN + pool
    gemm_rs<<<GRID_GEMM, 256>>>(h, W3, y, (const float*)p_dinv, nullptr, N_NODES, 0);
    aggregate<1><<<GRID_AGG, 256>>>(y, b3, nullptr, batch, gamma, beta, rmean, rvar);

    decode_g<<<(NG * NF + 255) / 256, 256>>>();

    // MLP head
    gemm_rs<<<(NG + 127) / 128, 256>>>((const float*)p_g, lw1, (float*)p_m1,
                                       nullptr, lb1, NG, 1);
    small_gemm<<<NG, 64>>>((const float*)p_m1, lw2, lb2, (float*)p_m2, 128, 64, 1);
    small_gemm<<<NG, 64>>>((const float*)p_m2, lw3, lb3, out, 64, NC, 0);
}